// round 5
// baseline (speedup 1.0000x reference)
#include <cuda_runtime.h>

// VectorP1FunctionSpace: evaluate two P1 FEM interpolants (wx, wy) on a
// structured 32x32 triangulation of [0,1]^2 via the exact analytic barycentric
// form (the reference's relu/min hat construction == barycentric coords).
//
// R4: overhead + latency-chain bound. Hide the weight-gather L2 hop by staging
// both weight tables (2 x 1089 floats = 8.7KB) into SMEM in parallel with the
// dependent x load: chain becomes max(DRAM_x, fill+bar) + LDS(29) instead of
// DRAM_x + L2(234). 2 points/thread, 32 CTAs x 256 threads (wide blocks were
// the fastest shape measured).

#define NXY    32
#define NYP1   33
#define NVERT  1089

__device__ __forceinline__ void eval_point(float px, float py,
                                           const float* __restrict__ swx,
                                           const float* __restrict__ swy,
                                           float& ox, float& oy)
{
    float sx = px * (float)NXY;
    float sy = py * (float)NXY;

    int i = (int)floorf(sx);
    int j = (int)floorf(sy);
    i = min(max(i, 0), NXY - 1);
    j = min(max(j, 0), NXY - 1);

    float fx = sx - (float)i;
    float fy = sy - (float)j;

    int v00 = i * NYP1 + j;
    int v11 = v00 + NYP1 + 1;

    // lower-right tri (v00,v10,v11): (1-fx, fx-fy, fy); else (v00,v11,v01): (1-fy, fx, fy-fx)
    bool  lower = (fx >= fy);
    float fm    = lower ? fx : fy;
    int   vb    = lower ? (v00 + NYP1) : v11;
    int   vc    = lower ? v11 : (v00 + 1);
    float l0    = 1.0f - fm;
    float l1    = lower ? (fx - fy) : fx;
    float l2    = lower ? fy : (fy - fx);

    ox = fmaf(l0, swx[v00], fmaf(l1, swx[vb], l2 * swx[vc]));
    oy = fmaf(l0, swy[v00], fmaf(l1, swy[vb], l2 * swy[vc]));
}

__global__ __launch_bounds__(256, 1)
void vp1_eval_kernel(const float4* __restrict__ x,
                     const float*  __restrict__ wx,
                     const float*  __restrict__ wy,
                     float4*       __restrict__ out,
                     int npairs)
{
    __shared__ float swx[NVERT];
    __shared__ float swy[NVERT];

    int tid = threadIdx.x;
    int idx = blockIdx.x * blockDim.x + tid;

    // 1) Dependent load first: two query points (16B). In flight while we fill.
    float4 p;
    bool active = (idx < npairs);
    if (active) p = x[idx];

    // 2) Independent SMEM fill of both weight tables (overlaps the x load).
    //    1089 floats each, 256 threads -> 5 strided loads per table.
    #pragma unroll
    for (int v = tid; v < NVERT; v += 256) {
        swx[v] = __ldg(&wx[v]);
        swy[v] = __ldg(&wy[v]);
    }
    __syncthreads();

    if (!active) return;

    float4 r;
    eval_point(p.x, p.y, swx, swy, r.x, r.y);
    eval_point(p.z, p.w, swx, swy, r.z, r.w);

    out[idx] = r;
}

extern "C" void kernel_launch(void* const* d_in, const int* in_sizes, int n_in,
                              void* d_out, int out_size)
{
    const float* x  = (const float*)d_in[0];   // [B, N, 2]
    // d_in[1] = W [V,6,2], d_in[2] = c [V,6]  -- unused (analytic form)
    const float* wx = (const float*)d_in[3];   // [V]
    const float* wy = (const float*)d_in[4];   // [V]
    float* out = (float*)d_out;                // [B, N, 2]

    int npairs = out_size / 4;                 // 2 points (4 floats) per thread

    int threads = 256;
    int blocks  = (npairs + threads - 1) / threads;   // 32 CTAs for 8192 pairs
    vp1_eval_kernel<<<blocks, threads>>>((const float4*)x, wx, wy,
                                         (float4*)out, npairs);
}

// round 6
// speedup vs baseline: 1.1011x; 1.1011x over previous
#include <cuda_runtime.h>

// VectorP1FunctionSpace: evaluate two P1 FEM interpolants (wx, wy) on a
// structured 32x32 triangulation of [0,1]^2 via the exact analytic barycentric
// form (the reference's relu/min hat construction == barycentric coords).
//
// R6: at the dur_us floor (~2.2us fixed replay overhead outside the kernel).
// Trim the in-kernel chain: weight tables staged interleaved as float2 in SMEM
// (3x LDS.64 per point instead of 6x LDS.32; half the STS count on the fill),
// fill overlapped with the dependent x load. 2 points/thread, 32 CTAs x 256.

#define NXY    32
#define NYP1   33
#define NVERT  1089

__device__ __forceinline__ void eval_point(float px, float py,
                                           const float2* __restrict__ sw,
                                           float& ox, float& oy)
{
    float sx = px * (float)NXY;
    float sy = py * (float)NXY;

    int i = (int)floorf(sx);
    int j = (int)floorf(sy);
    i = min(max(i, 0), NXY - 1);
    j = min(max(j, 0), NXY - 1);

    float fx = sx - (float)i;
    float fy = sy - (float)j;

    int v00 = i * NYP1 + j;
    int v11 = v00 + NYP1 + 1;

    // lower-right tri (v00,v10,v11): (1-fx, fx-fy, fy); else (v00,v11,v01): (1-fy, fx, fy-fx)
    bool  lower = (fx >= fy);
    float fm    = lower ? fx : fy;
    int   vb    = lower ? (v00 + NYP1) : v11;
    int   vc    = lower ? v11 : (v00 + 1);
    float l0    = 1.0f - fm;
    float l1    = lower ? (fx - fy) : fx;
    float l2    = lower ? fy : (fy - fx);

    float2 wa = sw[v00];
    float2 wb = sw[vb];
    float2 wc = sw[vc];

    ox = fmaf(l0, wa.x, fmaf(l1, wb.x, l2 * wc.x));
    oy = fmaf(l0, wa.y, fmaf(l1, wb.y, l2 * wc.y));
}

__global__ __launch_bounds__(256, 1)
void vp1_eval_kernel(const float4* __restrict__ x,
                     const float*  __restrict__ wx,
                     const float*  __restrict__ wy,
                     float4*       __restrict__ out,
                     int npairs)
{
    __shared__ float2 sw[NVERT];

    int tid = threadIdx.x;
    int idx = blockIdx.x * blockDim.x + tid;

    // 1) Dependent load first: two query points (16B). In flight during fill.
    float4 p;
    bool active = (idx < npairs);
    if (active) p = x[idx];

    // 2) Independent SMEM fill, interleaved (wx[v], wy[v]) -> sw[v].
    //    Coalesced LDG.32 pairs, STS.64 stores; overlaps the x load.
    #pragma unroll
    for (int v = tid; v < NVERT; v += 256) {
        sw[v] = make_float2(__ldg(&wx[v]), __ldg(&wy[v]));
    }
    __syncthreads();

    if (!active) return;

    float4 r;
    eval_point(p.x, p.y, sw, r.x, r.y);
    eval_point(p.z, p.w, sw, r.z, r.w);

    out[idx] = r;
}

extern "C" void kernel_launch(void* const* d_in, const int* in_sizes, int n_in,
                              void* d_out, int out_size)
{
    const float* x  = (const float*)d_in[0];   // [B, N, 2]
    // d_in[1] = W [V,6,2], d_in[2] = c [V,6]  -- unused (analytic form)
    const float* wx = (const float*)d_in[3];   // [V]
    const float* wy = (const float*)d_in[4];   // [V]
    float* out = (float*)d_out;                // [B, N, 2]

    int npairs = out_size / 4;                 // 2 points (4 floats) per thread

    int threads = 256;
    int blocks  = (npairs + threads - 1) / threads;   // 32 CTAs for 8192 pairs
    vp1_eval_kernel<<<blocks, threads>>>((const float4*)x, wx, wy,
                                         (float4*)out, npairs);
}